// round 11
// baseline (speedup 1.0000x reference)
#include <cuda_runtime.h>

#define T_ 1024
#define B_ 256
#define D_ 64
#define H_ 128
#define ROWS (T_*B_)

// Scratch (static __device__ arrays per allocation rules).
__device__ float g_U[ROWS * H_];
__device__ float g_S[ROWS * H_];

// ---------------- packed fp32x2 helpers (Blackwell FFMA2 path) ----------------
static __device__ __forceinline__ unsigned long long pack2(float x, float y) {
    unsigned long long r;
    asm("mov.b64 %0, {%1, %2};" : "=l"(r) : "f"(x), "f"(y));
    return r;
}
static __device__ __forceinline__ void unpack2(unsigned long long v, float& x, float& y) {
    asm("mov.b64 {%0, %1}, %2;" : "=f"(x), "=f"(y) : "l"(v));
}
static __device__ __forceinline__ unsigned long long fma2(unsigned long long a,
                                                          unsigned long long b,
                                                          unsigned long long c) {
    unsigned long long d;
    asm("fma.rn.f32x2 %0, %1, %2, %3;" : "=l"(d) : "l"(a), "l"(b), "l"(c));
    return d;
}

// tanh(x) = 1 - 2/(exp(2x)+1); MUFU.EX2 + MUFU.RCP, ~1e-6 error.
static __device__ __forceinline__ float fast_tanh(float x) {
    float e = __expf(2.0f * x);
    return 1.0f - __fdividef(2.0f, e + 1.0f);
}

// =====================================================================
// Fused two-stage GEMM:
//   stage1: Z = tanh(A[128 x K1] . W1[128 x K1]^T + b1)   (Z kept in SMEM)
//   stage2: out = Z[128 x 128] . W2[N2 x 128]^T + b2a (+b2b)
// One CTA computes 128 consecutive rows. 256 threads.
// Register tiling: stage1 4 rows x 16 cols / thread; stage2 RPT2 x 16.
// A staged row-major (stride K+4); W staged k-major; feat/Z row-major stride 132.
// =====================================================================
template<int K1, int N2, int RPT2>
__global__ void __launch_bounds__(256, 1) fused_gemm(
    const float* __restrict__ A,      // [ROWS][K1]
    const float* __restrict__ W1,     // [128][K1]
    const float* __restrict__ b1v,    // [128]
    const float* __restrict__ W2,     // [N2][128]
    const float* __restrict__ b2a,    // [N2]
    const float* __restrict__ b2b,    // [N2] or nullptr
    float* __restrict__ out)          // [ROWS][N2]
{
    extern __shared__ float sm[];
    float* W1s   = sm;                 // [K1][128] k-major
    float* W2s   = W1s + K1 * 128;     // [128][N2] k-major
    float* bias2 = W2s + 128 * N2;     // [N2]
    float* bias1 = bias2 + N2;         // [128]
    float* As    = bias1 + 128;        // stage1: [128][K1+4]; stage2: [128][132]

    const int tid = threadIdx.x;
    const long r0g = (long)blockIdx.x * 128;
    constexpr int S1 = K1 + 4;

    // ---- stage all inputs into SMEM ----
    // A tile, row-major (coalesced float4 reads, conflict-light STS.128)
    for (int i = tid; i < 128 * (K1 / 4); i += 256) {
        int r = i / (K1 / 4), kq = i % (K1 / 4);
        *(float4*)(As + r * S1 + kq * 4) =
            *(const float4*)(A + (r0g + r) * K1 + kq * 4);
    }
    // W1 -> k-major [K1][128]
    for (int i = tid; i < 128 * (K1 / 4); i += 256) {
        int n = i % 128, kq = i / 128;
        float4 v = *(const float4*)(W1 + (long)n * K1 + kq * 4);
        W1s[(kq * 4 + 0) * 128 + n] = v.x;
        W1s[(kq * 4 + 1) * 128 + n] = v.y;
        W1s[(kq * 4 + 2) * 128 + n] = v.z;
        W1s[(kq * 4 + 3) * 128 + n] = v.w;
    }
    // W2 -> k-major [128][N2]
    for (int i = tid; i < N2 * 32; i += 256) {
        int n = i % N2, kq = i / N2;
        float4 v = *(const float4*)(W2 + (long)n * 128 + kq * 4);
        W2s[(kq * 4 + 0) * N2 + n] = v.x;
        W2s[(kq * 4 + 1) * N2 + n] = v.y;
        W2s[(kq * 4 + 2) * N2 + n] = v.z;
        W2s[(kq * 4 + 3) * N2 + n] = v.w;
    }
    if (tid < N2)  bias2[tid] = b2a[tid] + (b2b ? b2b[tid] : 0.0f);
    if (tid < 128) bias1[tid] = b1v[tid];
    __syncthreads();

    // ---- stage 1: tanh(A . W1^T + b1) -> As (row-major, stride 132) ----
    {
        const int cg = tid & 7, rg = tid >> 3;
        const int c0 = cg * 16, rr = rg * 4;
        unsigned long long acc[4][8];
#pragma unroll
        for (int i = 0; i < 4; ++i)
#pragma unroll
            for (int j = 0; j < 8; ++j) acc[i][j] = 0ull;

#pragma unroll 2
        for (int k0 = 0; k0 < K1; k0 += 4) {
            float4 a[4];
#pragma unroll
            for (int i = 0; i < 4; ++i)
                a[i] = *(const float4*)(As + (rr + i) * S1 + k0);
#pragma unroll
            for (int kk = 0; kk < 4; ++kk) {
                const ulonglong2* bp = (const ulonglong2*)(W1s + (k0 + kk) * 128 + c0);
                ulonglong2 q0 = bp[0], q1 = bp[1], q2 = bp[2], q3 = bp[3];
                unsigned long long bb[8] = {q0.x, q0.y, q1.x, q1.y, q2.x, q2.y, q3.x, q3.y};
#pragma unroll
                for (int i = 0; i < 4; ++i) {
                    float av = (kk == 0) ? a[i].x : (kk == 1) ? a[i].y
                             : (kk == 2) ? a[i].z : a[i].w;
                    unsigned long long a2 = pack2(av, av);
#pragma unroll
                    for (int j = 0; j < 8; ++j)
                        acc[i][j] = fma2(bb[j], a2, acc[i][j]);
                }
            }
        }
        __syncthreads();  // everyone done reading As before overwrite
#pragma unroll
        for (int i = 0; i < 4; ++i) {
            float v[16];
#pragma unroll
            for (int j = 0; j < 8; ++j) unpack2(acc[i][j], v[2 * j], v[2 * j + 1]);
#pragma unroll
            for (int jj = 0; jj < 16; ++jj) v[jj] = fast_tanh(v[jj] + bias1[c0 + jj]);
#pragma unroll
            for (int q = 0; q < 4; ++q) {
                float4 o = {v[4 * q], v[4 * q + 1], v[4 * q + 2], v[4 * q + 3]};
                *(float4*)(As + (rr + i) * 132 + c0 + q * 4) = o;
            }
        }
    }
    __syncthreads();

    // ---- stage 2: Z . W2^T + bias2 -> out ----
    {
        constexpr int NCG = N2 / 16;
        const int cg = tid % NCG, rg = tid / NCG;
        const int c0 = cg * 16, rr = rg * RPT2;
        unsigned long long acc[RPT2][8];
#pragma unroll
        for (int i = 0; i < RPT2; ++i)
#pragma unroll
            for (int j = 0; j < 8; ++j) acc[i][j] = 0ull;

#pragma unroll 2
        for (int k0 = 0; k0 < 128; k0 += 4) {
            float4 a[RPT2];
#pragma unroll
            for (int i = 0; i < RPT2; ++i)
                a[i] = *(const float4*)(As + (rr + i) * 132 + k0);
#pragma unroll
            for (int kk = 0; kk < 4; ++kk) {
                const ulonglong2* bp = (const ulonglong2*)(W2s + (k0 + kk) * N2 + c0);
                ulonglong2 q0 = bp[0], q1 = bp[1], q2 = bp[2], q3 = bp[3];
                unsigned long long bb[8] = {q0.x, q0.y, q1.x, q1.y, q2.x, q2.y, q3.x, q3.y};
#pragma unroll
                for (int i = 0; i < RPT2; ++i) {
                    float av = (kk == 0) ? a[i].x : (kk == 1) ? a[i].y
                             : (kk == 2) ? a[i].z : a[i].w;
                    unsigned long long a2 = pack2(av, av);
#pragma unroll
                    for (int j = 0; j < 8; ++j)
                        acc[i][j] = fma2(bb[j], a2, acc[i][j]);
                }
            }
        }
#pragma unroll
        for (int i = 0; i < RPT2; ++i) {
            float v[16];
#pragma unroll
            for (int j = 0; j < 8; ++j) unpack2(acc[i][j], v[2 * j], v[2 * j + 1]);
#pragma unroll
            for (int jj = 0; jj < 16; ++jj) v[jj] += bias2[c0 + jj];
            float* op = out + (r0g + rr + i) * N2 + c0;
#pragma unroll
            for (int q = 0; q < 4; ++q) {
                float4 o = {v[4 * q], v[4 * q + 1], v[4 * q + 2], v[4 * q + 3]};
                *(float4*)(op + q * 4) = o;
            }
        }
    }
}

// ---------------- sequential recurrence (unchanged, near FMA floor) ----------------
__global__ void __launch_bounds__(128) rnn_scan(const float* __restrict__ U,
                                                const float* __restrict__ W_hh,
                                                float* __restrict__ S) {
    const int b = blockIdx.x;
    const int j = threadIdx.x;
    __shared__ __align__(16) float hbuf[2][H_];

    unsigned long long w2[64];
    const float4* wr = (const float4*)(W_hh + (size_t)j * H_);
#pragma unroll
    for (int i = 0; i < 32; ++i) {
        float4 v = wr[i];
        w2[2 * i]     = pack2(v.x, v.y);
        w2[2 * i + 1] = pack2(v.z, v.w);
    }

    hbuf[0][j] = 0.0f;
    S[(size_t)b * H_ + j] = 0.0f;  // S[t=0] = 0
    __syncthreads();

    const float* Ub = U + (size_t)b * H_ + j;
    float u0 = Ub[0];
    float u1 = Ub[(size_t)B_ * H_];
    int cur = 0;

#pragma unroll 1
    for (int t = 0; t < T_ - 1; ++t) {
        float u2 = 0.0f;
        if (t + 2 <= T_ - 2) u2 = Ub[(size_t)(t + 2) * B_ * H_];

        const ulonglong2* hv = (const ulonglong2*)hbuf[cur];
        unsigned long long accA = 0ull, accB = 0ull;
#pragma unroll
        for (int i = 0; i < 32; ++i) {
            ulonglong2 hh = hv[i];
            accA = fma2(w2[2 * i], hh.x, accA);
            accB = fma2(w2[2 * i + 1], hh.y, accB);
        }
        float a0, a1, c0, c1;
        unpack2(accA, a0, a1);
        unpack2(accB, c0, c1);
        float hnew = fast_tanh(u0 + ((a0 + a1) + (c0 + c1)));

        hbuf[cur ^ 1][j] = hnew;
        S[((size_t)(t + 1) * B_ + b) * H_ + j] = hnew;

        u0 = u1;
        u1 = u2;
        cur ^= 1;
        __syncthreads();
    }
}

extern "C" void kernel_launch(void* const* d_in, const int* in_sizes, int n_in,
                              void* d_out, int out_size) {
    const float* x    = (const float*)d_in[0];
    const float* W_x  = (const float*)d_in[1];
    const float* b_x  = (const float*)d_in[2];
    const float* W_ih = (const float*)d_in[3];
    const float* b_ih = (const float*)d_in[4];
    const float* W_hh = (const float*)d_in[5];
    const float* b_hh = (const float*)d_in[6];
    const float* W_h  = (const float*)d_in[7];
    const float* b_h  = (const float*)d_in[8];
    const float* W_g  = (const float*)d_in[9];
    const float* b_g  = (const float*)d_in[10];
    float* y = (float*)d_out;

    float *U, *S;
    cudaGetSymbolAddress((void**)&U, g_U);
    cudaGetSymbolAddress((void**)&S, g_S);

    // SMEM: W1s + W2s + bias2 + bias1 + As(128*132)
    const size_t smem1 = (size_t)(64 * 128 + 128 * 128 + 128 + 128 + 128 * 132) * 4;  // ~163KB
    const size_t smem2 = (size_t)(128 * 128 + 128 * 64 + 64 + 128 + 128 * 132) * 4;   // ~163KB
    cudaFuncSetAttribute(fused_gemm<64, 128, 4>,
                         cudaFuncAttributeMaxDynamicSharedMemorySize, (int)smem1);
    cudaFuncSetAttribute(fused_gemm<128, 64, 2>,
                         cudaFuncAttributeMaxDynamicSharedMemorySize, (int)smem2);

    // F1: U = tanh(x W_x^T + b_x) W_ih^T + b_ih + b_hh   (feat never hits HBM)
    fused_gemm<64, 128, 4><<<ROWS / 128, 256, smem1>>>(x, W_x, b_x, W_ih, b_ih, b_hh, U);
    // Scan: S[t+1] = tanh(U[t] + S[t] W_hh^T), S[0] = 0
    rnn_scan<<<B_, 128>>>(U, W_hh, S);
    // F2: y = tanh(S W_h^T + b_h) W_g^T + b_g            (Z never hits HBM)
    fused_gemm<128, 64, 2><<<ROWS / 128, 256, smem2>>>(S, W_h, b_h, W_g, b_g, nullptr, y);
}